// round 13
// baseline (speedup 1.0000x reference)
#include <cuda_runtime.h>

typedef unsigned long long ull;

#define GT 256
#define HTH 256
#define M_FLOATS (64*320)
#define MS_FLOATS (5*64*64)
#define W1_FLOATS (64*16)
#define N_NODES 25000
#define E_MAX 400000

__device__ float  g_Ms[MS_FLOATS];            // [s][m][o=u*8+w] folded weights
__device__ float  g_W1t[W1_FLOATS];           // [m][16] W1^T / 4
__device__ double g_acc[N_NODES * 32];        // segment-sum accumulator
__device__ float  g_hT[64 * (size_t)E_MAX];   // [m][e] radial MLP outputs, k-major
__device__ float4 g_n[E_MAX];                 // unit edge vectors

__device__ __forceinline__ ull pk2(float a, float b){ ull r; asm("mov.b64 %0, {%1,%2};" : "=l"(r) : "f"(a), "f"(b)); return r; }
__device__ __forceinline__ ull fma2(ull a, ull b, ull c){ ull d; asm("fma.rn.f32x2 %0, %1, %2, %3;" : "=l"(d) : "l"(a), "l"(b), "l"(c)); return d; }
__device__ __forceinline__ float2 upk(ull a){ float2 f; asm("mov.b64 {%0,%1}, %2;" : "=f"(f.x), "=f"(f.y) : "l"(a)); return f; }

// ---------------- prep: fold W2 + scales into g_Ms[5][64][64] ----------------
__global__ void prep_kernel(const float* __restrict__ W1, const float* __restrict__ W2)
{
    int idx = blockIdx.x * blockDim.x + threadIdx.x;
    const float a0  = 0.17677669529663687f;   // 1/sqrt(32)
    const float a1  = 0.27386127875258304f;   // sqrt(3/40)
    const float a1s = 0.15811388300841897f;   // a1/sqrt(3)
    const float aE  = 0.33541019662496846f;   // a1*sqrt(1.5)
    if (idx < M_FLOATS) {
        int m = idx / 320, o = idx % 320;
        int sect = o >> 6, r = o & 63, u = r >> 3, w = r & 7;
        const float* Vm = W2 + m * 576;
        float eval = aE * 0.125f * Vm[512 + u * 8 + w];
        float val; int s;
        if (sect < 4) {
            int t0 = sect * 128 + u * 16 + w;
            float sc = (sect <= 1) ? a0 : (sect == 2 ? a1 : a1s);
            val = sc * 0.125f * (Vm[t0] + Vm[t0 + 8]);
            if (sect == 3) { val -= eval * (1.0f/3.0f); s = 4; }  // D' -> slot 4
            else s = sect;                                        // A,B,C -> 0,1,2
        } else {
            val = eval; s = 3;                                    // E -> slot 3
        }
        g_Ms[s * 4096 + m * 64 + r] = val;
    }
    if (idx < W1_FLOATS) {
        int m = idx >> 4, j = idx & 15;
        g_W1t[m * 16 + j] = W1[j * 64 + m] * 0.25f;
    }
}

__global__ void zero_acc_kernel(int n)
{
    int i = blockIdx.x * blockDim.x + threadIdx.x;
    if (i < n) g_acc[i] = 0.0;
}

__global__ void finish_kernel(float* __restrict__ out, int N)
{
    int i = blockIdx.x * blockDim.x + threadIdx.x;
    if (i < N * 32) {
        int c = i & 31;
        float v = (float)g_acc[i];
        out[i] = (c < 8) ? (v / (1.0f + __expf(-v))) : v;
    }
}

// ---------------- radial MLP + edge geometry precompute (k-major h) ----------------
__global__ void h_kernel(const float* __restrict__ pos, const int* __restrict__ ei, int E)
{
    __shared__ float sW1[W1_FLOATS];
    for (int i = threadIdx.x; i < W1_FLOATS; i += HTH) sW1[i] = g_W1t[i];
    __syncthreads();

    int e = blockIdx.x * HTH + threadIdx.x;
    if (e >= E) return;

    int r = ei[e];
    int c = ei[E + e];
    float evx = pos[3*r]   - pos[3*c];
    float evy = pos[3*r+1] - pos[3*c+1];
    float evz = pos[3*r+2] - pos[3*c+2];
    float d2  = evx*evx + evy*evy + evz*evz + 1e-12f;
    float d   = sqrtf(d2);
    float inv = 1.0f / d;
    g_n[e] = make_float4(evx*inv, evy*inv, evz*inv, 0.0f);

    float rb[16];
    #pragma unroll
    for (int j = 0; j < 16; j++) {
        float t = d - (float)j * (1.0f/3.0f);
        rb[j] = __expf(-4.5f * t * t);
    }

    #pragma unroll 1
    for (int m = 0; m < 64; m++) {
        const float4* wrow = (const float4*)(sW1 + m * 16);
        float4 w0 = wrow[0], w1 = wrow[1], w2 = wrow[2], w3 = wrow[3];
        float acc0 = rb[0]*w0.x + rb[1]*w0.y + rb[2]*w0.z + rb[3]*w0.w;
        float acc1 = rb[4]*w1.x + rb[5]*w1.y + rb[6]*w1.z + rb[7]*w1.w;
        float acc2 = rb[8]*w2.x + rb[9]*w2.y + rb[10]*w2.z + rb[11]*w2.w;
        float acc3 = rb[12]*w3.x + rb[13]*w3.y + rb[14]*w3.z + rb[15]*w3.w;
        g_hT[(size_t)m * E_MAX + e] = fmaxf((acc0 + acc1) + (acc2 + acc3), 0.0f);
    }
}

// ---------------- fused tile kernel: 256 thr, 128-edge tile, double-buffered M ----------------
// smem: sh_h[64][128] (32KB) | sh_M[2][64][64] (32KB) | sh_C[128][68] (34KB) = 98KB -> 2 CTAs/SM
#define SH_H 0
#define SH_M 8192
#define SH_C 16384
#define C_STRIDE 68
#define SM_TOTAL ((16384 + 128*C_STRIDE) * 4)

__global__ void __launch_bounds__(GT, 2) edge_kernel(
    const float* __restrict__ x, const int* __restrict__ ei, int E)
{
    extern __shared__ float sm[];
    int tid = threadIdx.x;
    int e_base = blockIdx.x * 128;

    // fill h tile [64][128] (2048 float4 / 256 thr = 8 each) + M section 0 (1024 float4 / 256 = 4 each)
    {
        float4* dst = (float4*)(sm + SH_H);
        int c0 = e_base >> 2;
        #pragma unroll
        for (int it = 0; it < 8; it++) {
            int i = tid + it * GT;
            int m = i >> 5, c = i & 31;
            dst[i] = __ldg((const float4*)(g_hT + (size_t)m * E_MAX) + c0 + c);
        }
        float4* dstM = (float4*)(sm + SH_M);
        const float4* Mg = (const float4*)g_Ms;
        #pragma unroll
        for (int it = 0; it < 4; it++)
            dstM[tid + it * GT] = __ldg(Mg + tid + it * GT);
    }

    // per-thread epilogue edge data (lower half only)
    bool lower = (tid < 128);
    int e = e_base + tid;
    bool ve = lower && (e < E);
    int ec = ve ? e : 0;
    int r = ei[ec];
    float4 nf = g_n[ec];
    const float4* xp = (const float4*)(x + (size_t)r * 32);

    float p[8], q[8];
    if (lower) {
        float4 a = xp[0], b = xp[1];
        p[0]=a.x; p[1]=a.y; p[2]=a.z; p[3]=a.w;
        p[4]=b.x; p[5]=b.y; p[6]=b.z; p[7]=b.w;
        float4 A=xp[2], B=xp[3], C=xp[4], D=xp[5], Ee=xp[6], F=xp[7];
        q[0] = A.x*nf.x + A.y*nf.y + A.z*nf.z;
        q[1] = A.w*nf.x + B.x*nf.y + B.y*nf.z;
        q[2] = B.z*nf.x + B.w*nf.y + C.x*nf.z;
        q[3] = C.y*nf.x + C.z*nf.y + C.w*nf.z;
        q[4] = D.x*nf.x + D.y*nf.y + D.z*nf.z;
        q[5] = D.w*nf.x + Ee.x*nf.y + Ee.y*nf.z;
        q[6] = Ee.z*nf.x + Ee.w*nf.y + F.x*nf.z;
        q[7] = F.y*nf.x + F.z*nf.y + F.w*nf.z;
    }

    int eg = tid >> 3, og = tid & 7;          // eg 0..31 (4 edges each), og 0..7
    const float* hB = sm + SH_H + eg * 4;
    const float* mB0 = sm + SH_M + og * 8;

    ull outS[4] = {0,0,0,0};
    ull cn[4]   = {0,0,0,0};
    ull oV[3][4] = {{0,0,0,0},{0,0,0,0},{0,0,0,0}};

    __syncthreads();   // h + M0 visible

    #pragma unroll 1
    for (int s = 0; s < 5; s++) {
        const float* mB = mB0 + (s & 1) * 4096;

        // GEMM: acc[4 edges][4 out-pairs]
        ull acc[4][4];
        #pragma unroll
        for (int i = 0; i < 4; i++)
            #pragma unroll
            for (int j = 0; j < 4; j++) acc[i][j] = 0ULL;

        #pragma unroll 4
        for (int k = 0; k < 64; k++) {
            ulonglong2 m01 = *(const ulonglong2*)(mB + k * 64);
            ulonglong2 m23 = *(const ulonglong2*)(mB + k * 64 + 4);
            float4 h0 = *(const float4*)(hB + k * 128);
            ull hp;
            hp = pk2(h0.x,h0.x);
            acc[0][0]=fma2(m01.x,hp,acc[0][0]); acc[0][1]=fma2(m01.y,hp,acc[0][1]);
            acc[0][2]=fma2(m23.x,hp,acc[0][2]); acc[0][3]=fma2(m23.y,hp,acc[0][3]);
            hp = pk2(h0.y,h0.y);
            acc[1][0]=fma2(m01.x,hp,acc[1][0]); acc[1][1]=fma2(m01.y,hp,acc[1][1]);
            acc[1][2]=fma2(m23.x,hp,acc[1][2]); acc[1][3]=fma2(m23.y,hp,acc[1][3]);
            hp = pk2(h0.z,h0.z);
            acc[2][0]=fma2(m01.x,hp,acc[2][0]); acc[2][1]=fma2(m01.y,hp,acc[2][1]);
            acc[2][2]=fma2(m23.x,hp,acc[2][2]); acc[2][3]=fma2(m23.y,hp,acc[2][3]);
            hp = pk2(h0.w,h0.w);
            acc[3][0]=fma2(m01.x,hp,acc[3][0]); acc[3][1]=fma2(m01.y,hp,acc[3][1]);
            acc[3][2]=fma2(m23.x,hp,acc[3][2]); acc[3][3]=fma2(m23.y,hp,acc[3][3]);
        }

        // store C tile (rows 16B-aligned via C_STRIDE=68)
        #pragma unroll
        for (int i = 0; i < 4; i++) {
            float* cp = sm + SH_C + (eg * 4 + i) * C_STRIDE + og * 8;
            ulonglong2 t0; t0.x = acc[i][0]; t0.y = acc[i][1];
            ulonglong2 t1; t1.x = acc[i][2]; t1.y = acc[i][3];
            *(ulonglong2*)cp = t0;
            *(ulonglong2*)(cp + 4) = t1;
        }
        __syncthreads();

        if (lower) {
            // epilogue: edge = tid reads g[u][w] for this section
            const float* gC = sm + SH_C + tid * C_STRIDE;
            if (s == 0 || s == 1) {
                #pragma unroll
                for (int u = 0; u < 8; u++) {
                    ulonglong2 g01 = *(const ulonglong2*)(gC + u * 8);
                    ulonglong2 g23 = *(const ulonglong2*)(gC + u * 8 + 4);
                    float f = (s == 1) ? q[u] : p[u];
                    ull fp = pk2(f, f);
                    outS[0]=fma2(g01.x,fp,outS[0]); outS[1]=fma2(g01.y,fp,outS[1]);
                    outS[2]=fma2(g23.x,fp,outS[2]); outS[3]=fma2(g23.y,fp,outS[3]);
                }
            } else if (s == 2 || s == 3) {
                #pragma unroll
                for (int u = 0; u < 8; u++) {
                    ulonglong2 g01 = *(const ulonglong2*)(gC + u * 8);
                    ulonglong2 g23 = *(const ulonglong2*)(gC + u * 8 + 4);
                    float f = (s == 3) ? q[u] : p[u];
                    ull fp = pk2(f, f);
                    cn[0]=fma2(g01.x,fp,cn[0]); cn[1]=fma2(g01.y,fp,cn[1]);
                    cn[2]=fma2(g23.x,fp,cn[2]); cn[3]=fma2(g23.y,fp,cn[3]);
                }
            } else {
                float4 A=xp[2], B=xp[3], C=xp[4], D=xp[5], Ee=xp[6], F=xp[7];
                float xv[8][3];
                xv[0][0]=A.x;  xv[0][1]=A.y;  xv[0][2]=A.z;
                xv[1][0]=A.w;  xv[1][1]=B.x;  xv[1][2]=B.y;
                xv[2][0]=B.z;  xv[2][1]=B.w;  xv[2][2]=C.x;
                xv[3][0]=C.y;  xv[3][1]=C.z;  xv[3][2]=C.w;
                xv[4][0]=D.x;  xv[4][1]=D.y;  xv[4][2]=D.z;
                xv[5][0]=D.w;  xv[5][1]=Ee.x; xv[5][2]=Ee.y;
                xv[6][0]=Ee.z; xv[6][1]=Ee.w; xv[6][2]=F.x;
                xv[7][0]=F.y;  xv[7][1]=F.z;  xv[7][2]=F.w;
                #pragma unroll
                for (int u = 0; u < 8; u++) {
                    ulonglong2 g01 = *(const ulonglong2*)(gC + u * 8);
                    ulonglong2 g23 = *(const ulonglong2*)(gC + u * 8 + 4);
                    #pragma unroll
                    for (int k3 = 0; k3 < 3; k3++) {
                        ull fp = pk2(xv[u][k3], xv[u][k3]);
                        oV[k3][0]=fma2(g01.x,fp,oV[k3][0]); oV[k3][1]=fma2(g01.y,fp,oV[k3][1]);
                        oV[k3][2]=fma2(g23.x,fp,oV[k3][2]); oV[k3][3]=fma2(g23.y,fp,oV[k3][3]);
                    }
                }
            }
        } else {
            // upper half: prefetch next M section into alternate buffer
            if (s < 4) {
                const float4* Mg = (const float4*)(g_Ms + (s + 1) * 4096);
                float4* dstM = (float4*)(sm + SH_M + ((s + 1) & 1) * 4096);
                int t2 = tid - 128;
                #pragma unroll
                for (int it = 0; it < 8; it++)
                    dstM[t2 + it * 128] = __ldg(Mg + t2 + it * 128);
            }
        }
        __syncthreads();   // C consumed + next M ready
    }

    // n outer-product on accumulated coefficient
    {
        ull nn0 = pk2(nf.x, nf.x), nn1 = pk2(nf.y, nf.y), nn2 = pk2(nf.z, nf.z);
        #pragma unroll
        for (int wp = 0; wp < 4; wp++) {
            oV[0][wp] = fma2(cn[wp], nn0, oV[0][wp]);
            oV[1][wp] = fma2(cn[wp], nn1, oV[1][wp]);
            oV[2][wp] = fma2(cn[wp], nn2, oV[2][wp]);
        }
    }

    if (ve) {
        double* y = g_acc + (size_t)r * 32;
        #pragma unroll
        for (int wp = 0; wp < 4; wp++) {
            float2 sv = upk(outS[wp]);
            atomicAdd(y + wp*2,     (double)sv.x);
            atomicAdd(y + wp*2 + 1, (double)sv.y);
        }
        #pragma unroll
        for (int wp = 0; wp < 4; wp++) {
            #pragma unroll
            for (int k3 = 0; k3 < 3; k3++) {
                float2 vv = upk(oV[k3][wp]);
                atomicAdd(y + 8 + (wp*2)*3   + k3, (double)vv.x);
                atomicAdd(y + 8 + (wp*2+1)*3 + k3, (double)vv.y);
            }
        }
    }
}

extern "C" void kernel_launch(void* const* d_in, const int* in_sizes, int n_in,
                              void* d_out, int out_size)
{
    const float* x   = (const float*)d_in[0];
    const float* pos = (const float*)d_in[1];
    const int*   ei  = (const int*)d_in[2];
    const float* W1  = (const float*)d_in[3];
    const float* W2  = (const float*)d_in[4];
    float* out = (float*)d_out;

    int E = in_sizes[2] / 2;
    int N = in_sizes[1] / 3;

    prep_kernel<<<(M_FLOATS + 255) / 256, 256>>>(W1, W2);
    zero_acc_kernel<<<(N * 32 + 255) / 256, 256>>>(N * 32);
    h_kernel<<<(E + HTH - 1) / HTH, HTH>>>(pos, ei, E);

    int blocks = (E + 127) / 128;
    cudaFuncSetAttribute(edge_kernel, cudaFuncAttributeMaxDynamicSharedMemorySize, SM_TOTAL);
    edge_kernel<<<blocks, GT, SM_TOTAL>>>(x, ei, E);

    finish_kernel<<<(N * 32 + 255) / 256, 256>>>(out, N);
}

// round 15
// speedup vs baseline: 1.4753x; 1.4753x over previous
#include <cuda_runtime.h>
#include <cstdint>

typedef unsigned long long ull;

#define GT 128
#define HTH 256
#define M_FLOATS (64*320)
#define MS_FLOATS (5*64*64)
#define W1_FLOATS (64*16)
#define N_NODES 25000
#define E_MAX 400000

__device__ float  g_Ms[MS_FLOATS];            // [s][m][o=u*8+w] folded weights, section-major
__device__ float  g_W1t[W1_FLOATS];           // [m][16] W1^T / 4
__device__ double g_acc[N_NODES * 32];        // segment-sum accumulator
__device__ float  g_hT[64 * (size_t)E_MAX];   // [m][e] radial MLP outputs, k-major
__device__ float4 g_n[E_MAX];                 // unit edge vectors

__device__ __forceinline__ ull pk2(float a, float b){ ull r; asm("mov.b64 %0, {%1,%2};" : "=l"(r) : "f"(a), "f"(b)); return r; }
__device__ __forceinline__ ull fma2(ull a, ull b, ull c){ ull d; asm("fma.rn.f32x2 %0, %1, %2, %3;" : "=l"(d) : "l"(a), "l"(b), "l"(c)); return d; }
__device__ __forceinline__ float2 upk(ull a){ float2 f; asm("mov.b64 {%0,%1}, %2;" : "=f"(f.x), "=f"(f.y) : "l"(a)); return f; }
__device__ __forceinline__ uint32_t smem_u32(const void* p){ uint32_t a; asm("{ .reg .u64 t; cvta.to.shared.u64 t, %1; cvt.u32.u64 %0, t; }" : "=r"(a) : "l"(p)); return a; }
#define CP_ASYNC16(dst_u32, src_ptr) \
    asm volatile("cp.async.cg.shared.global [%0], [%1], 16;" :: "r"(dst_u32), "l"(src_ptr) : "memory")
#define CP_COMMIT()  asm volatile("cp.async.commit_group;" ::: "memory")
#define CP_WAIT0()   asm volatile("cp.async.wait_group 0;" ::: "memory")

// ---------------- prep: fold W2 + scales into g_Ms[5][64][64] ----------------
__global__ void prep_kernel(const float* __restrict__ W1, const float* __restrict__ W2)
{
    int idx = blockIdx.x * blockDim.x + threadIdx.x;
    const float a0  = 0.17677669529663687f;   // 1/sqrt(32)
    const float a1  = 0.27386127875258304f;   // sqrt(3/40)
    const float a1s = 0.15811388300841897f;   // a1/sqrt(3)
    const float aE  = 0.33541019662496846f;   // a1*sqrt(1.5)
    if (idx < M_FLOATS) {
        int m = idx / 320, o = idx % 320;
        int sect = o >> 6, r = o & 63, u = r >> 3, w = r & 7;
        const float* Vm = W2 + m * 576;
        float eval = aE * 0.125f * Vm[512 + u * 8 + w];
        float val; int s;
        if (sect < 4) {
            int t0 = sect * 128 + u * 16 + w;
            float sc = (sect <= 1) ? a0 : (sect == 2 ? a1 : a1s);
            val = sc * 0.125f * (Vm[t0] + Vm[t0 + 8]);
            if (sect == 3) { val -= eval * (1.0f/3.0f); s = 4; }  // D' -> slot 4
            else s = sect;                                        // A,B,C -> 0,1,2
        } else {
            val = eval; s = 3;                                    // E -> slot 3
        }
        g_Ms[s * 4096 + m * 64 + r] = val;
    }
    if (idx < W1_FLOATS) {
        int m = idx >> 4, j = idx & 15;
        g_W1t[m * 16 + j] = W1[j * 64 + m] * 0.25f;
    }
}

__global__ void zero_acc_kernel(int n)
{
    int i = blockIdx.x * blockDim.x + threadIdx.x;
    if (i < n) g_acc[i] = 0.0;
}

__global__ void finish_kernel(float* __restrict__ out, int N)
{
    int i = blockIdx.x * blockDim.x + threadIdx.x;
    if (i < N * 32) {
        int c = i & 31;
        float v = (float)g_acc[i];
        out[i] = (c < 8) ? (v / (1.0f + __expf(-v))) : v;
    }
}

// ---------------- radial MLP + edge geometry precompute (k-major h) ----------------
__global__ void h_kernel(const float* __restrict__ pos, const int* __restrict__ ei, int E)
{
    __shared__ float sW1[W1_FLOATS];
    for (int i = threadIdx.x; i < W1_FLOATS; i += HTH) sW1[i] = g_W1t[i];
    __syncthreads();

    int e = blockIdx.x * HTH + threadIdx.x;
    if (e >= E) return;

    int r = ei[e];
    int c = ei[E + e];
    float evx = pos[3*r]   - pos[3*c];
    float evy = pos[3*r+1] - pos[3*c+1];
    float evz = pos[3*r+2] - pos[3*c+2];
    float d2  = evx*evx + evy*evy + evz*evz + 1e-12f;
    float d   = sqrtf(d2);
    float inv = 1.0f / d;
    g_n[e] = make_float4(evx*inv, evy*inv, evz*inv, 0.0f);

    float rb[16];
    #pragma unroll
    for (int j = 0; j < 16; j++) {
        float t = d - (float)j * (1.0f/3.0f);
        rb[j] = __expf(-4.5f * t * t);
    }

    #pragma unroll 1
    for (int m = 0; m < 64; m++) {
        const float4* wrow = (const float4*)(sW1 + m * 16);
        float4 w0 = wrow[0], w1 = wrow[1], w2 = wrow[2], w3 = wrow[3];
        float acc0 = rb[0]*w0.x + rb[1]*w0.y + rb[2]*w0.z + rb[3]*w0.w;
        float acc1 = rb[4]*w1.x + rb[5]*w1.y + rb[6]*w1.z + rb[7]*w1.w;
        float acc2 = rb[8]*w2.x + rb[9]*w2.y + rb[10]*w2.z + rb[11]*w2.w;
        float acc3 = rb[12]*w3.x + rb[13]*w3.y + rb[14]*w3.z + rb[15]*w3.w;
        g_hT[(size_t)m * E_MAX + e] = fmaxf((acc0 + acc1) + (acc2 + acc3), 0.0f);
    }
}

// ---------------- fused tile kernel: GEMM (128e x 64o, K=64) + per-edge epilogue ----------------
// smem: sh_h[64][128] (32KB) | sh_M[2][64][64] (32KB, cp.async double-buffered) | sh_C[128][68] (34KB)
#define SH_H 0
#define SH_M 8192
#define SH_C 16384
#define C_STRIDE 68
#define SM_TOTAL ((16384 + 128*C_STRIDE) * 4)

__global__ void __launch_bounds__(GT, 2) edge_kernel(
    const float* __restrict__ x, const int* __restrict__ ei, int E)
{
    extern __shared__ float sm[];
    int tid = threadIdx.x;
    int e_base = blockIdx.x * 128;
    uint32_t sb = smem_u32(sm);

    // prefetch M section 0 via cp.async (1024 float4 / 128 thr = 8 each)
    {
        const float4* Mg = (const float4*)g_Ms;
        uint32_t dst = sb + SH_M * 4 + tid * 16;
        #pragma unroll
        for (int it = 0; it < 8; it++)
            CP_ASYNC16(dst + it * 128 * 16, Mg + tid + it * 128);
        CP_COMMIT();
    }

    // load h tile [64][128] (coalesced float4)
    {
        float4* dst = (float4*)(sm + SH_H);
        int c0 = e_base >> 2;
        #pragma unroll
        for (int it = 0; it < 16; it++) {
            int i = tid + it * 128;
            int m = i >> 5, c = i & 31;
            dst[i] = __ldg((const float4*)(g_hT + (size_t)m * E_MAX) + c0 + c);
        }
    }

    // per-thread edge data (epilogue edge = e_base + tid)
    int e = e_base + tid;
    bool ve = (e < E);
    int ec = ve ? e : 0;
    int r = ei[ec];
    float4 nf = g_n[ec];
    const float4* xp = (const float4*)(x + (size_t)r * 32);

    float p[8], q[8];
    {
        float4 a = xp[0], b = xp[1];
        p[0]=a.x; p[1]=a.y; p[2]=a.z; p[3]=a.w;
        p[4]=b.x; p[5]=b.y; p[6]=b.z; p[7]=b.w;
        float4 A=xp[2], B=xp[3], C=xp[4], D=xp[5], Ee=xp[6], F=xp[7];
        q[0] = A.x*nf.x + A.y*nf.y + A.z*nf.z;
        q[1] = A.w*nf.x + B.x*nf.y + B.y*nf.z;
        q[2] = B.z*nf.x + B.w*nf.y + C.x*nf.z;
        q[3] = C.y*nf.x + C.z*nf.y + C.w*nf.z;
        q[4] = D.x*nf.x + D.y*nf.y + D.z*nf.z;
        q[5] = D.w*nf.x + Ee.x*nf.y + Ee.y*nf.z;
        q[6] = Ee.z*nf.x + Ee.w*nf.y + F.x*nf.z;
        q[7] = F.y*nf.x + F.z*nf.y + F.w*nf.z;
    }

    int eg = tid >> 3, og = tid & 7;
    const float* hB = sm + SH_H + eg * 8;
    const float* mB0 = sm + SH_M + og * 8;

    ull outS[4] = {0,0,0,0};
    ull cn[4]   = {0,0,0,0};
    ull oV[3][4] = {{0,0,0,0},{0,0,0,0},{0,0,0,0}};

    CP_WAIT0();
    __syncthreads();   // h + M0 visible

    #pragma unroll 1
    for (int s = 0; s < 5; s++) {
        // prefetch next M section into alternate buffer (hidden under GEMM)
        if (s < 4) {
            const float4* Mg = (const float4*)(g_Ms + (s + 1) * 4096);
            uint32_t dst = sb + (SH_M + ((s + 1) & 1) * 4096) * 4 + tid * 16;
            #pragma unroll
            for (int it = 0; it < 8; it++)
                CP_ASYNC16(dst + it * 128 * 16, Mg + tid + it * 128);
            CP_COMMIT();
        }

        const float* mB = mB0 + (s & 1) * 4096;

        // GEMM: acc[8 edges][4 out-pairs]
        ull acc[8][4];
        #pragma unroll
        for (int i = 0; i < 8; i++)
            #pragma unroll
            for (int j = 0; j < 4; j++) acc[i][j] = 0ULL;

        #pragma unroll 4
        for (int k = 0; k < 64; k++) {
            ulonglong2 m01 = *(const ulonglong2*)(mB + k * 64);
            ulonglong2 m23 = *(const ulonglong2*)(mB + k * 64 + 4);
            float4 h0 = *(const float4*)(hB + k * 128);
            float4 h1 = *(const float4*)(hB + k * 128 + 4);
            ull hp;
            hp = pk2(h0.x,h0.x);
            acc[0][0]=fma2(m01.x,hp,acc[0][0]); acc[0][1]=fma2(m01.y,hp,acc[0][1]);
            acc[0][2]=fma2(m23.x,hp,acc[0][2]); acc[0][3]=fma2(m23.y,hp,acc[0][3]);
            hp = pk2(h0.y,h0.y);
            acc[1][0]=fma2(m01.x,hp,acc[1][0]); acc[1][1]=fma2(m01.y,hp,acc[1][1]);
            acc[1][2]=fma2(m23.x,hp,acc[1][2]); acc[1][3]=fma2(m23.y,hp,acc[1][3]);
            hp = pk2(h0.z,h0.z);
            acc[2][0]=fma2(m01.x,hp,acc[2][0]); acc[2][1]=fma2(m01.y,hp,acc[2][1]);
            acc[2][2]=fma2(m23.x,hp,acc[2][2]); acc[2][3]=fma2(m23.y,hp,acc[2][3]);
            hp = pk2(h0.w,h0.w);
            acc[3][0]=fma2(m01.x,hp,acc[3][0]); acc[3][1]=fma2(m01.y,hp,acc[3][1]);
            acc[3][2]=fma2(m23.x,hp,acc[3][2]); acc[3][3]=fma2(m23.y,hp,acc[3][3]);
            hp = pk2(h1.x,h1.x);
            acc[4][0]=fma2(m01.x,hp,acc[4][0]); acc[4][1]=fma2(m01.y,hp,acc[4][1]);
            acc[4][2]=fma2(m23.x,hp,acc[4][2]); acc[4][3]=fma2(m23.y,hp,acc[4][3]);
            hp = pk2(h1.y,h1.y);
            acc[5][0]=fma2(m01.x,hp,acc[5][0]); acc[5][1]=fma2(m01.y,hp,acc[5][1]);
            acc[5][2]=fma2(m23.x,hp,acc[5][2]); acc[5][3]=fma2(m23.y,hp,acc[5][3]);
            hp = pk2(h1.z,h1.z);
            acc[6][0]=fma2(m01.x,hp,acc[6][0]); acc[6][1]=fma2(m01.y,hp,acc[6][1]);
            acc[6][2]=fma2(m23.x,hp,acc[6][2]); acc[6][3]=fma2(m23.y,hp,acc[6][3]);
            hp = pk2(h1.w,h1.w);
            acc[7][0]=fma2(m01.x,hp,acc[7][0]); acc[7][1]=fma2(m01.y,hp,acc[7][1]);
            acc[7][2]=fma2(m23.x,hp,acc[7][2]); acc[7][3]=fma2(m23.y,hp,acc[7][3]);
        }

        // store C tile (rows 16B-aligned via C_STRIDE=68)
        #pragma unroll
        for (int i = 0; i < 8; i++) {
            float* cp = sm + SH_C + (eg * 8 + i) * C_STRIDE + og * 8;
            ulonglong2 t0; t0.x = acc[i][0]; t0.y = acc[i][1];
            ulonglong2 t1; t1.x = acc[i][2]; t1.y = acc[i][3];
            *(ulonglong2*)cp = t0;
            *(ulonglong2*)(cp + 4) = t1;
        }
        if (s < 4) CP_WAIT0();   // my prefetch landed
        __syncthreads();          // C visible + everyone's prefetch landed

        // epilogue: edge = tid reads g[u][w] for this section
        const float* gC = sm + SH_C + tid * C_STRIDE;
        if (s == 0 || s == 1) {
            #pragma unroll
            for (int u = 0; u < 8; u++) {
                ulonglong2 g01 = *(const ulonglong2*)(gC + u * 8);
                ulonglong2 g23 = *(const ulonglong2*)(gC + u * 8 + 4);
                float f = (s == 1) ? q[u] : p[u];
                ull fp = pk2(f, f);
                outS[0]=fma2(g01.x,fp,outS[0]); outS[1]=fma2(g01.y,fp,outS[1]);
                outS[2]=fma2(g23.x,fp,outS[2]); outS[3]=fma2(g23.y,fp,outS[3]);
            }
        } else if (s == 2 || s == 3) {
            #pragma unroll
            for (int u = 0; u < 8; u++) {
                ulonglong2 g01 = *(const ulonglong2*)(gC + u * 8);
                ulonglong2 g23 = *(const ulonglong2*)(gC + u * 8 + 4);
                float f = (s == 3) ? q[u] : p[u];
                ull fp = pk2(f, f);
                cn[0]=fma2(g01.x,fp,cn[0]); cn[1]=fma2(g01.y,fp,cn[1]);
                cn[2]=fma2(g23.x,fp,cn[2]); cn[3]=fma2(g23.y,fp,cn[3]);
            }
        } else {
            float4 A=xp[2], B=xp[3], C=xp[4], D=xp[5], Ee=xp[6], F=xp[7];
            float xv[8][3];
            xv[0][0]=A.x;  xv[0][1]=A.y;  xv[0][2]=A.z;
            xv[1][0]=A.w;  xv[1][1]=B.x;  xv[1][2]=B.y;
            xv[2][0]=B.z;  xv[2][1]=B.w;  xv[2][2]=C.x;
            xv[3][0]=C.y;  xv[3][1]=C.z;  xv[3][2]=C.w;
            xv[4][0]=D.x;  xv[4][1]=D.y;  xv[4][2]=D.z;
            xv[5][0]=D.w;  xv[5][1]=Ee.x; xv[5][2]=Ee.y;
            xv[6][0]=Ee.z; xv[6][1]=Ee.w; xv[6][2]=F.x;
            xv[7][0]=F.y;  xv[7][1]=F.z;  xv[7][2]=F.w;
            #pragma unroll
            for (int u = 0; u < 8; u++) {
                ulonglong2 g01 = *(const ulonglong2*)(gC + u * 8);
                ulonglong2 g23 = *(const ulonglong2*)(gC + u * 8 + 4);
                #pragma unroll
                for (int k3 = 0; k3 < 3; k3++) {
                    ull fp = pk2(xv[u][k3], xv[u][k3]);
                    oV[k3][0]=fma2(g01.x,fp,oV[k3][0]); oV[k3][1]=fma2(g01.y,fp,oV[k3][1]);
                    oV[k3][2]=fma2(g23.x,fp,oV[k3][2]); oV[k3][3]=fma2(g23.y,fp,oV[k3][3]);
                }
            }
        }
        __syncthreads();   // C consumed before next section overwrites
    }

    // n outer-product on accumulated coefficient
    {
        ull nn0 = pk2(nf.x, nf.x), nn1 = pk2(nf.y, nf.y), nn2 = pk2(nf.z, nf.z);
        #pragma unroll
        for (int wp = 0; wp < 4; wp++) {
            oV[0][wp] = fma2(cn[wp], nn0, oV[0][wp]);
            oV[1][wp] = fma2(cn[wp], nn1, oV[1][wp]);
            oV[2][wp] = fma2(cn[wp], nn2, oV[2][wp]);
        }
    }

    if (ve) {
        double* y = g_acc + (size_t)r * 32;
        #pragma unroll
        for (int wp = 0; wp < 4; wp++) {
            float2 sv = upk(outS[wp]);
            atomicAdd(y + wp*2,     (double)sv.x);
            atomicAdd(y + wp*2 + 1, (double)sv.y);
        }
        #pragma unroll
        for (int wp = 0; wp < 4; wp++) {
            #pragma unroll
            for (int k3 = 0; k3 < 3; k3++) {
                float2 vv = upk(oV[k3][wp]);
                atomicAdd(y + 8 + (wp*2)*3   + k3, (double)vv.x);
                atomicAdd(y + 8 + (wp*2+1)*3 + k3, (double)vv.y);
            }
        }
    }
}

extern "C" void kernel_launch(void* const* d_in, const int* in_sizes, int n_in,
                              void* d_out, int out_size)
{
    const float* x   = (const float*)d_in[0];
    const float* pos = (const float*)d_in[1];
    const int*   ei  = (const int*)d_in[2];
    const float* W1  = (const float*)d_in[3];
    const float* W2  = (const float*)d_in[4];
    float* out = (float*)d_out;

    int E = in_sizes[2] / 2;
    int N = in_sizes[1] / 3;

    prep_kernel<<<(M_FLOATS + 255) / 256, 256>>>(W1, W2);
    zero_acc_kernel<<<(N * 32 + 255) / 256, 256>>>(N * 32);
    h_kernel<<<(E + HTH - 1) / HTH, HTH>>>(pos, ei, E);

    int blocks = (E + 127) / 128;
    cudaFuncSetAttribute(edge_kernel, cudaFuncAttributeMaxDynamicSharedMemorySize, SM_TOTAL);
    edge_kernel<<<blocks, GT, SM_TOTAL>>>(x, ei, E);

    finish_kernel<<<(N * 32 + 255) / 256, 256>>>(out, N);
}